// round 8
// baseline (speedup 1.0000x reference)
#include <cuda_runtime.h>
#include <cstdint>

#define BATCH 64
#define HH 512
#define WW 512
#define TILE_H 64
#define NROWT 8
#define NCOLT 2
#define NPART (BATCH * NROWT * NCOLT)  // 1024
#define NTH 128
#define NSTEP (TILE_H + 10)            // 74 staged rows

typedef unsigned long long u64;

__device__ float g_partials[NPART];
__device__ unsigned int g_ticket = 0;

// ---- packed f32x2 helpers ----
__device__ __forceinline__ u64 pk2(float lo, float hi) {
    u64 r; asm("mov.b64 %0, {%1, %2};" : "=l"(r) : "f"(lo), "f"(hi)); return r;
}
__device__ __forceinline__ void upk2(u64 v, float& lo, float& hi) {
    asm("mov.b64 {%0, %1}, %2;" : "=f"(lo), "=f"(hi) : "l"(v));
}
__device__ __forceinline__ u64 f2mul(u64 a, u64 b) {
    u64 d; asm("mul.rn.f32x2 %0, %1, %2;" : "=l"(d) : "l"(a), "l"(b)); return d;
}
__device__ __forceinline__ u64 f2add(u64 a, u64 b) {
    u64 d; asm("add.rn.f32x2 %0, %1, %2;" : "=l"(d) : "l"(a), "l"(b)); return d;
}
__device__ __forceinline__ u64 f2fma(u64 a, u64 b, u64 c) {
    u64 d; asm("fma.rn.f32x2 %0, %1, %2, %3;" : "=l"(d) : "l"(a), "l"(b), "l"(c)); return d;
}

__global__ __launch_bounds__(NTH, 3)
void ssim_map_kernel(const float* __restrict__ x, const float* __restrict__ y,
                     const float* __restrict__ win, float* __restrict__ out)
{
    // exchange: [buf][field][idx]; idx 0..3 left-halo pairs, 4..131 main, 132..135 right-halo
    __shared__ u64 EX[2][4][136];            // 8704 B
    // raw halo ring (warp-0 private): [slot][x|y][pair 0..7]
    __shared__ u64 HR[11][2][8];             // 1408 B
    __shared__ float swarp[4];
    __shared__ int s_last;

    const int t  = threadIdx.x;
    const int tl = t & 31;
    const int w  = t >> 5;
    const int ct = blockIdx.x & 1;
    const int rt = blockIdx.x >> 1;
    const int b  = blockIdx.y;
    const int c0 = ct * 256;
    const int r0 = rt * TILE_H;
    const float* xb = x + (size_t)b * HH * WW;
    const float* yb = y + (size_t)b * HH * WW;

    const bool lvalid = (c0 > 0);
    const bool rvalid = (c0 + 256 < WW);

    // 1D taps g[i] = sum_j w2d[i][j] (sum g == 1), packed (g,g)
    u64 g2[11];
    #pragma unroll
    for (int i = 0; i < 11; ++i) {
        float s = 0.f;
        #pragma unroll
        for (int j = 0; j < 11; ++j) s += win[i * 11 + j];
        g2[i] = pk2(s, s);
    }

    const u64 HC1  = pk2(5e-5f, 5e-5f);     // C1/2
    const u64 HC2  = pk2(4.5e-4f, 4.5e-4f); // C2/2
    const u64 FC1  = pk2(1e-4f, 1e-4f);     // C1
    const u64 FC2  = pk2(9e-4f, 9e-4f);     // C2
    const u64 NEG1 = pk2(-1.f, -1.f);

    // main raw load (8B, aligned)
    auto ldmain = [&](const float* base, int rin) -> u64 {
        if ((unsigned)rin < (unsigned)HH)
            return *(const u64*)(base + (size_t)rin * WW + c0 + 2 * t);
        return 0ull;
    };
    // halo raw load for t<8: t<4 -> left pair t, t in 4..7 -> right pair t-4
    auto ldhalo = [&](const float* base, int rin) -> u64 {
        bool v = (t < 4) ? lvalid : rvalid;
        int col = (t < 4) ? (c0 - 8 + 2 * t) : (c0 + 256 + 2 * (t - 4));
        if (v && (unsigned)rin < (unsigned)HH)
            return *(const u64*)(base + (size_t)rin * WW + col);
        return 0ull;
    };

    // vertical phase accumulators: 11 x 4 packed fields
    u64 AX[11], AY[11], AS[11], AP[11];
    #pragma unroll
    for (int i = 0; i < 11; ++i) { AX[i] = 0; AY[i] = 0; AS[i] = 0; AP[i] = 0; }

    // prefetch pipeline, distance 2 (rows for steps 0,1: rin = r0-5, r0-4)
    u64 px0 = ldmain(xb, r0 - 5), py0 = ldmain(yb, r0 - 5);
    u64 px1 = ldmain(xb, r0 - 4), py1 = ldmain(yb, r0 - 4);
    u64 hx0 = 0, hy0 = 0, hx1 = 0, hy1 = 0;
    if (t < 8) {
        hx0 = ldhalo(xb, r0 - 5); hy0 = ldhalo(yb, r0 - 5);
        hx1 = ldhalo(xb, r0 - 4); hy1 = ldhalo(yb, r0 - 4);
    }

    float acc = 0.f;

    for (int blk = 0; blk < 7; ++blk) {
        #pragma unroll
        for (int ph = 0; ph < 11; ++ph) {
            const int s = blk * 11 + ph;
            if (s < NSTEP) {
                // ---- phase A: consume current raw row, prefetch s+2 ----
                u64 cx = px0, cy = py0;
                px0 = px1; py0 = py1;
                {
                    int rin2 = r0 + s - 3;              // row for step s+2
                    px1 = ldmain(xb, rin2);
                    py1 = ldmain(yb, rin2);
                }
                if (t < 8) {
                    // stage current halo raw into ring slot ph
                    HR[ph][0][t] = hx0;
                    HR[ph][1][t] = hy0;
                    hx0 = hx1; hy0 = hy1;
                    int rin2 = r0 + s - 3;
                    hx1 = ldhalo(xb, rin2);
                    hy1 = ldhalo(yb, rin2);
                }
                __syncwarp();   // warp0: HR writes visible to halo tasks below

                u64 ss = f2fma(cy, cy, f2mul(cx, cx));   // x^2 + y^2
                u64 pp = f2mul(cx, cy);                  // x*y

                // update 11 phase accumulators (fresh slot ph: assign)
                AX[ph] = f2mul(g2[0], cx);
                AY[ph] = f2mul(g2[0], cy);
                AS[ph] = f2mul(g2[0], ss);
                AP[ph] = f2mul(g2[0], pp);
                #pragma unroll
                for (int k = 1; k < 11; ++k) {
                    const int sl = (ph - k + 11) % 11;
                    AX[sl] = f2fma(g2[k], cx, AX[sl]);
                    AY[sl] = f2fma(g2[k], cy, AY[sl]);
                    AS[sl] = f2fma(g2[k], ss, AS[sl]);
                    AP[sl] = f2fma(g2[k], pp, AP[sl]);
                }

                // ---- phase B: output row o = s-10 complete in slot (ph+1)%11 ----
                if (s >= 10) {
                    const int c = (ph + 1) % 11;
                    const int buf = s & 1;
                    // main exchange writes
                    EX[buf][0][4 + t] = AX[c];
                    EX[buf][1][4 + t] = AY[c];
                    EX[buf][2][4 + t] = AS[c];
                    EX[buf][3][4 + t] = AP[c];

                    // halo vertical sums (t<8), from warp-0-private ring
                    if (t < 8) {
                        bool v = (t < 4) ? lvalid : rvalid;
                        u64 hmx = 0, hmy = 0, hms = 0, hmp = 0;
                        if (v) {
                            #pragma unroll
                            for (int k = 0; k < 11; ++k) {
                                const int sl = (ph + 1 + k) % 11;
                                u64 hx = HR[sl][0][t];
                                u64 hy = HR[sl][1][t];
                                hmx = f2fma(g2[k], hx, hmx);
                                hmy = f2fma(g2[k], hy, hmy);
                                u64 s2 = f2fma(hy, hy, f2mul(hx, hx));
                                hms = f2fma(g2[k], s2, hms);
                                hmp = f2fma(g2[k], f2mul(hx, hy), hmp);
                            }
                        }
                        int idx = (t < 4) ? t : (128 + t);   // 0..3 / 132..135
                        EX[buf][0][idx] = hmx;
                        EX[buf][1][idx] = hmy;
                        EX[buf][2][idx] = hms;
                        EX[buf][3][idx] = hmp;
                    }
                    __syncthreads();

                    // horizontal 11-tap on 4 fields from exchange
                    u64 H[4];
                    #pragma unroll
                    for (int f = 0; f < 4; ++f) {
                        u64 A0 = EX[buf][f][t + 1];
                        u64 A1 = EX[buf][f][t + 2];
                        u64 A2 = EX[buf][f][t + 3];
                        u64 A3 = EX[buf][f][t + 4];
                        u64 A4 = EX[buf][f][t + 5];
                        u64 A5 = EX[buf][f][t + 6];
                        u64 A6 = EX[buf][f][t + 7];
                        float a0l, a0h, a1l, a1h, a2l, a2h, a3l, a3h;
                        float a4l, a4h, a5l, a5h, a6l, a6h;
                        upk2(A0, a0l, a0h); upk2(A1, a1l, a1h); upk2(A2, a2l, a2h);
                        upk2(A3, a3l, a3h); upk2(A4, a4l, a4h); upk2(A5, a5l, a5h);
                        upk2(A6, a6l, a6h);
                        u64 h = f2mul(g2[0], pk2(a0h, a1l));      // tap 0
                        h = f2fma(g2[1],  A1,            h);      // tap 1
                        h = f2fma(g2[2],  pk2(a1h, a2l), h);      // tap 2
                        h = f2fma(g2[3],  A2,            h);      // tap 3
                        h = f2fma(g2[4],  pk2(a2h, a3l), h);      // tap 4
                        h = f2fma(g2[5],  A3,            h);      // tap 5
                        h = f2fma(g2[6],  pk2(a3h, a4l), h);      // tap 6
                        h = f2fma(g2[7],  A4,            h);      // tap 7
                        h = f2fma(g2[8],  pk2(a4h, a5l), h);      // tap 8
                        h = f2fma(g2[9],  A5,            h);      // tap 9
                        h = f2fma(g2[10], pk2(a5h, a6l), h);      // tap 10
                        H[f] = h;
                    }

                    // SSIM pointwise
                    u64 mx = H[0], my = H[1], ms = H[2], mp = H[3];
                    u64 mx2 = f2mul(mx, mx);
                    u64 my2 = f2mul(my, my);
                    u64 mxy = f2mul(mx, my);
                    u64 msq = f2add(mx2, my2);
                    u64 vp  = f2fma(msq, NEG1, ms);    // sigma_x^2 + sigma_y^2
                    u64 vxy = f2fma(mxy, NEG1, mp);    // sigma_xy
                    u64 t1  = f2add(mxy, HC1);
                    u64 t2  = f2add(vxy, HC2);
                    u64 num = f2mul(t1, t2);           // ssim = 4*num/den
                    u64 t3  = f2add(msq, FC1);
                    u64 t4  = f2add(vp,  FC2);
                    u64 den = f2mul(t3, t4);
                    float n0, n1, d0, d1;
                    upk2(num, n0, n1);
                    upk2(den, d0, d1);
                    acc += __fdividef(n0, d0) + __fdividef(n1, d1);
                }
            }
        }
    }

    // ---- deterministic per-CTA reduction -> partial ----
    #pragma unroll
    for (int o = 16; o; o >>= 1) acc += __shfl_down_sync(0xFFFFFFFFu, acc, o);
    if (tl == 0) swarp[w] = acc;
    __syncthreads();
    if (t == 0) {
        float s = (swarp[0] + swarp[1]) + (swarp[2] + swarp[3]);
        g_partials[blockIdx.y * (NROWT * NCOLT) + blockIdx.x] = s;
        __threadfence();
        unsigned old = atomicAdd(&g_ticket, 1u);
        s_last = (old == NPART - 1);
    }
    __syncthreads();

    // ---- last CTA: fixed-order final reduction (deterministic) ----
    if (s_last) {
        __threadfence();
        float v = 0.f;
        #pragma unroll
        for (int k = 0; k < NPART / NTH; ++k)
            v += g_partials[t + NTH * k];
        #pragma unroll
        for (int o = 16; o; o >>= 1) v += __shfl_down_sync(0xFFFFFFFFu, v, o);
        __syncthreads();
        if (tl == 0) swarp[w] = v;
        __syncthreads();
        if (t == 0) {
            float s = (swarp[0] + swarp[1]) + (swarp[2] + swarp[3]);
            // accumulated terms were num/4 / den -> scale by 4 / (B*H*W)
            out[0] = s * (4.0f / 16777216.0f);
            g_ticket = 0;   // reset for next graph replay
        }
    }
}

extern "C" void kernel_launch(void* const* d_in, const int* in_sizes, int n_in,
                              void* d_out, int out_size)
{
    const float* x   = (const float*)d_in[0];
    const float* y   = (const float*)d_in[1];
    const float* win = (const float*)d_in[2];
    float* out = (float*)d_out;

    dim3 grid(NROWT * NCOLT, BATCH);   // (16, 64) = 1024 CTAs
    ssim_map_kernel<<<grid, NTH>>>(x, y, win, out);
}

// round 10
// speedup vs baseline: 1.4376x; 1.4376x over previous
#include <cuda_runtime.h>
#include <cstdint>

#define BATCH 64
#define HH 512
#define WW 512
#define TILE_H 128
#define NROWT (HH / TILE_H)            // 4
#define NSTRIP 8                       // 64-col warp strips
#define NPART (BATCH * NROWT * NSTRIP) // 2048
#define DEPTH 8
#define DIST 6
#define NSTEP (TILE_H + 10)            // 138 staged rows per tile

typedef unsigned long long u64;

__device__ float g_partials[NPART];
__device__ unsigned int g_ticket = 0;

// ---- packed f32x2 helpers (Blackwell FFMA2 path, PTX-only) ----
__device__ __forceinline__ u64 pk2(float lo, float hi) {
    u64 r; asm("mov.b64 %0, {%1, %2};" : "=l"(r) : "f"(lo), "f"(hi)); return r;
}
__device__ __forceinline__ void upk2(u64 v, float& lo, float& hi) {
    asm("mov.b64 {%0, %1}, %2;" : "=f"(lo), "=f"(hi) : "l"(v));
}
__device__ __forceinline__ u64 f2mul(u64 a, u64 b) {
    u64 d; asm("mul.rn.f32x2 %0, %1, %2;" : "=l"(d) : "l"(a), "l"(b)); return d;
}
__device__ __forceinline__ u64 f2add(u64 a, u64 b) {
    u64 d; asm("add.rn.f32x2 %0, %1, %2;" : "=l"(d) : "l"(a), "l"(b)); return d;
}
__device__ __forceinline__ u64 f2fma(u64 a, u64 b, u64 c) {
    u64 d; asm("fma.rn.f32x2 %0, %1, %2, %3;" : "=l"(d) : "l"(a), "l"(b), "l"(c)); return d;
}

__global__ __launch_bounds__(32, 9)
void ssim_map_kernel(const float* __restrict__ x, const float* __restrict__ y,
                     const float* __restrict__ win, float* __restrict__ out)
{
    // warp-private staging ring: [slot][field][8 halo + 64 + 8 halo]  (5120 B)
    // 16B alignment REQUIRED for cp.async 16B destinations.
    __shared__ __align__(16) float sbuf[DEPTH][2][80];

    const int t     = threadIdx.x;          // 0..31
    const int strip = blockIdx.x & 7;
    const int rt    = blockIdx.x >> 3;
    const int b     = blockIdx.y;
    const int cw    = strip * 64;           // first output column of this warp
    const int r0    = rt * TILE_H;
    const float* xb = x + (size_t)b * HH * WW;
    const float* yb = y + (size_t)b * HH * WW;

    const bool lvalid = (cw > 0);
    const bool rvalid = (cw + 64 < WW);

    // zero ONLY invalid-side halos once (never written again)
    if (t < DEPTH) {
        float4 z = make_float4(0.f, 0.f, 0.f, 0.f);
        #pragma unroll
        for (int f = 0; f < 2; ++f) {
            if (!lvalid) { *(float4*)&sbuf[t][f][0]  = z; *(float4*)&sbuf[t][f][4]  = z; }
            if (!rvalid) { *(float4*)&sbuf[t][f][72] = z; *(float4*)&sbuf[t][f][76] = z; }
        }
    }

    // 1D taps g[i] = sum_j w2d[i][j] (sum g == 1), packed (g,g)
    u64 g2[11];
    #pragma unroll
    for (int i = 0; i < 11; ++i) {
        float s = 0.f;
        #pragma unroll
        for (int j = 0; j < 11; ++j) s += win[i * 11 + j];
        g2[i] = pk2(s, s);
    }

    const u64 HC1  = pk2(5e-5f, 5e-5f);     // C1/2
    const u64 HC2  = pk2(4.5e-4f, 4.5e-4f); // C2/2
    const u64 FC1  = pk2(1e-4f, 1e-4f);     // C1
    const u64 FC2  = pk2(9e-4f, 9e-4f);     // C2
    const u64 NEG1 = pk2(-1.f, -1.f);

    // lane roles for fills (computed once)
    const int  l16    = t & 15;
    const int  hf     = (t >> 2) & 1;        // halo field: 0=x, 1=y
    const int  hs     = (t >> 1) & 1;        // halo side: 0=left, 1=right
    const int  hk     = t & 1;               // halo chunk within side
    const bool hv     = (t < 8) && (hs ? rvalid : lvalid);
    const int  hdoff  = (hs ? 72 : 0) + hk * 4;
    const int  hcol   = hs ? (cw + 64 + hk * 4) : (cw - 8 + hk * 4);
    const float* mplane = (t < 16) ? xb : yb;
    const float* hplane = hf ? yb : xb;

    // ---- row fill: 16B cp.async; zeros for out-of-image rows ----
    auto fill_row = [&](int p) {
        int slot = p & 7;
        int r_in = r0 - 5 + p;
        float* bx = sbuf[slot][0];
        float* by = sbuf[slot][1];
        float* mdst = ((t < 16) ? bx : by) + 8 + l16 * 4;
        float* hdst = (hf ? by : bx) + hdoff;
        if ((unsigned)r_in < (unsigned)HH) {
            const float* msrc = mplane + (size_t)r_in * WW + cw + l16 * 4;
            unsigned d = (unsigned)__cvta_generic_to_shared(mdst);
            asm volatile("cp.async.cg.shared.global [%0], [%1], 16;" :: "r"(d), "l"(msrc) : "memory");
            if (hv) {
                const float* hsrc = hplane + (size_t)r_in * WW + hcol;
                unsigned dh = (unsigned)__cvta_generic_to_shared(hdst);
                asm volatile("cp.async.cg.shared.global [%0], [%1], 16;" :: "r"(dh), "l"(hsrc) : "memory");
            }
        } else {
            float4 z = make_float4(0.f, 0.f, 0.f, 0.f);
            *(float4*)mdst = z;
            if (hv) *(float4*)hdst = z;
        }
    };

    // prologue: prefetch rows 0..DIST-1, one commit group each
    #pragma unroll
    for (int p = 0; p < DIST; ++p) {
        fill_row(p);
        asm volatile("cp.async.commit_group;" ::: "memory");
    }

    // register ring: 11 rows x 4 packed fields (mu_x, mu_y, x^2+y^2, x*y)
    u64 RX[11], RY[11], RS[11], RP[11];
    float acc = 0.f;

    for (int blk = 0; blk < 13; ++blk) {
        #pragma unroll
        for (int ph = 0; ph < 11; ++ph) {
            const int pr = blk * 11 + ph;
            if (pr < NSTEP) {
                // warp-private pipeline: slot (pr+6)&7 = (pr-2)&7 was consumed
                // by this warp two iterations ago -> no block barrier needed.
                int pf = pr + DIST;
                if (pf < NSTEP) fill_row(pf);
                asm volatile("cp.async.commit_group;" ::: "memory");
                asm volatile("cp.async.wait_group %0;" :: "n"(DIST) : "memory");
                __syncwarp();   // make warp-mates' staged row visible

                // stage 14 floats per field into registers (aligned float2 loads)
                const float2* xv = (const float2*)sbuf[pr & 7][0] + (t + 1);
                const float2* yv = (const float2*)sbuf[pr & 7][1] + (t + 1);
                float xr[14], yr[14];
                #pragma unroll
                for (int i = 0; i < 7; ++i) {
                    float2 a = xv[i]; xr[2 * i] = a.x; xr[2 * i + 1] = a.y;
                    float2 c = yv[i]; yr[2 * i] = c.x; yr[2 * i + 1] = c.y;
                }

                // horizontal 11-tap conv, packed over column pair (cw+2t, cw+2t+1)
                u64 hx = 0, hy = 0, hsum = 0, hp = 0;
                #pragma unroll
                for (int j = 0; j < 11; ++j) {
                    u64 ax = pk2(xr[1 + j], xr[2 + j]);
                    u64 ay = pk2(yr[1 + j], yr[2 + j]);
                    hx = f2fma(g2[j], ax, hx);
                    hy = f2fma(g2[j], ay, hy);
                    u64 ss = f2mul(ax, ax);
                    ss = f2fma(ay, ay, ss);
                    hsum = f2fma(g2[j], ss, hsum);
                    u64 pp = f2mul(ax, ay);
                    hp = f2fma(g2[j], pp, hp);
                }
                RX[ph] = hx; RY[ph] = hy; RS[ph] = hsum; RP[ph] = hp;

                // vertical 11-tap conv + SSIM once ring is warm
                if (pr >= 10) {
                    u64 mx = f2mul(g2[0], RX[(ph + 1) % 11]);
                    u64 my = f2mul(g2[0], RY[(ph + 1) % 11]);
                    u64 sp = f2mul(g2[0], RS[(ph + 1) % 11]);
                    u64 sx = f2mul(g2[0], RP[(ph + 1) % 11]);
                    #pragma unroll
                    for (int k = 1; k < 11; ++k) {
                        const int sl = (ph + 1 + k) % 11;
                        mx = f2fma(g2[k], RX[sl], mx);
                        my = f2fma(g2[k], RY[sl], my);
                        sp = f2fma(g2[k], RS[sl], sp);
                        sx = f2fma(g2[k], RP[sl], sx);
                    }
                    u64 mx2 = f2mul(mx, mx);
                    u64 my2 = f2mul(my, my);
                    u64 mxy = f2mul(mx, my);
                    u64 msq = f2add(mx2, my2);
                    u64 vp  = f2fma(msq, NEG1, sp);    // sigma_x^2 + sigma_y^2
                    u64 vxy = f2fma(mxy, NEG1, sx);    // sigma_xy
                    u64 t1  = f2add(mxy, HC1);
                    u64 t2  = f2add(vxy, HC2);
                    u64 num = f2mul(t1, t2);           // ssim = 4*num/den
                    u64 t3  = f2add(msq, FC1);
                    u64 t4  = f2add(vp,  FC2);
                    u64 den = f2mul(t3, t4);
                    float n0, n1, d0, d1;
                    upk2(num, n0, n1);
                    upk2(den, d0, d1);
                    acc += __fdividef(n0, d0) + __fdividef(n1, d1);
                }
            }
        }
    }

    // ---- deterministic warp reduction -> partial ----
    #pragma unroll
    for (int o = 16; o; o >>= 1) acc += __shfl_down_sync(0xFFFFFFFFu, acc, o);

    int last = 0;
    if (t == 0) {
        g_partials[blockIdx.y * (NROWT * NSTRIP) + blockIdx.x] = acc;
        __threadfence();
        unsigned old = atomicAdd(&g_ticket, 1u);
        last = (old == NPART - 1);
    }
    last = __shfl_sync(0xFFFFFFFFu, last, 0);

    // ---- last warp: fixed-order final reduction (deterministic) ----
    if (last) {
        __threadfence();
        float v = 0.f;
        #pragma unroll
        for (int k = 0; k < NPART / 32; ++k)
            v += g_partials[t + 32 * k];
        #pragma unroll
        for (int o = 16; o; o >>= 1) v += __shfl_down_sync(0xFFFFFFFFu, v, o);
        if (t == 0) {
            // accumulated terms were num/4 / den -> scale by 4 / (B*H*W)
            out[0] = v * (4.0f / 16777216.0f);
            g_ticket = 0;   // reset for next graph replay
        }
    }
}

extern "C" void kernel_launch(void* const* d_in, const int* in_sizes, int n_in,
                              void* d_out, int out_size)
{
    const float* x   = (const float*)d_in[0];
    const float* y   = (const float*)d_in[1];
    const float* win = (const float*)d_in[2];
    float* out = (float*)d_out;

    dim3 grid(NROWT * NSTRIP, BATCH);   // (32, 64) = 2048 one-warp CTAs
    ssim_map_kernel<<<grid, 32>>>(x, y, win, out);
}

// round 13
// speedup vs baseline: 1.7105x; 1.1898x over previous
#include <cuda_runtime.h>
#include <cstdint>

#define BATCH 64
#define HH 512
#define WW 512
#define TILE_H 64
#define NROWT (HH / TILE_H)            // 8
#define NSTRIP 8                       // 64-col warp strips
#define NPART (BATCH * NROWT * NSTRIP) // 4096
#define DEPTH 8
#define DIST 6
#define NSTEP (TILE_H + 10)            // 74 staged rows per tile

typedef unsigned long long u64;

__device__ float g_partials[NPART];
__device__ unsigned int g_ticket = 0;

// ---- packed f32x2 helpers (Blackwell FFMA2 path, PTX-only) ----
__device__ __forceinline__ u64 pk2(float lo, float hi) {
    u64 r; asm("mov.b64 %0, {%1, %2};" : "=l"(r) : "f"(lo), "f"(hi)); return r;
}
__device__ __forceinline__ void upk2(u64 v, float& lo, float& hi) {
    asm("mov.b64 {%0, %1}, %2;" : "=f"(lo), "=f"(hi) : "l"(v));
}
__device__ __forceinline__ u64 f2mul(u64 a, u64 b) {
    u64 d; asm("mul.rn.f32x2 %0, %1, %2;" : "=l"(d) : "l"(a), "l"(b)); return d;
}
__device__ __forceinline__ u64 f2add(u64 a, u64 b) {
    u64 d; asm("add.rn.f32x2 %0, %1, %2;" : "=l"(d) : "l"(a), "l"(b)); return d;
}
__device__ __forceinline__ u64 f2fma(u64 a, u64 b, u64 c) {
    u64 d; asm("fma.rn.f32x2 %0, %1, %2, %3;" : "=l"(d) : "l"(a), "l"(b), "l"(c)); return d;
}

__global__ __launch_bounds__(32, 14)
void ssim_map_kernel(const float* __restrict__ x, const float* __restrict__ y,
                     const float* __restrict__ win, float* __restrict__ out)
{
    // warp-private staging ring: [slot][field][8 halo + 64 + 8 halo]  (5120 B)
    // 16B alignment REQUIRED for cp.async 16B destinations.
    __shared__ __align__(16) float sbuf[DEPTH][2][80];

    const int t     = threadIdx.x;          // 0..31
    const int strip = blockIdx.x & 7;
    const int rt    = blockIdx.x >> 3;
    const int b     = blockIdx.y;
    const int cw    = strip * 64;           // first output column of this warp
    const int r0    = rt * TILE_H;
    const float* xb = x + (size_t)b * HH * WW;
    const float* yb = y + (size_t)b * HH * WW;

    const bool lvalid = (cw > 0);
    const bool rvalid = (cw + 64 < WW);

    // zero ONLY invalid-side halos once (never written again)
    if (t < DEPTH) {
        float4 z = make_float4(0.f, 0.f, 0.f, 0.f);
        #pragma unroll
        for (int f = 0; f < 2; ++f) {
            if (!lvalid) { *(float4*)&sbuf[t][f][0]  = z; *(float4*)&sbuf[t][f][4]  = z; }
            if (!rvalid) { *(float4*)&sbuf[t][f][72] = z; *(float4*)&sbuf[t][f][76] = z; }
        }
    }

    // 1D taps g[i] = sum_j w2d[i][j] (sum g == 1), packed (g,g)
    u64 g2[11];
    #pragma unroll
    for (int i = 0; i < 11; ++i) {
        float s = 0.f;
        #pragma unroll
        for (int j = 0; j < 11; ++j) s += win[i * 11 + j];
        g2[i] = pk2(s, s);
    }

    const u64 HC1  = pk2(5e-5f, 5e-5f);     // C1/2
    const u64 HC2  = pk2(4.5e-4f, 4.5e-4f); // C2/2
    const u64 FC1  = pk2(1e-4f, 1e-4f);     // C1
    const u64 FC2  = pk2(9e-4f, 9e-4f);     // C2
    const u64 NEG1 = pk2(-1.f, -1.f);

    // lane roles for fills (computed once)
    const int  l16    = t & 15;
    const int  hf     = (t >> 2) & 1;        // halo field: 0=x, 1=y
    const int  hs     = (t >> 1) & 1;        // halo side: 0=left, 1=right
    const int  hk     = t & 1;               // halo chunk within side
    const bool hv     = (t < 8) && (hs ? rvalid : lvalid);
    const int  hdoff  = (hs ? 72 : 0) + hk * 4;
    const int  hcol   = hs ? (cw + 64 + hk * 4) : (cw - 8 + hk * 4);
    const float* mplane = (t < 16) ? xb : yb;
    const float* hplane = hf ? yb : xb;

    // running fill state (sequential rows): advance pointers by WW per fill
    int          fr   = r0 - 5;                                    // next row to fill
    int          fs   = 0;                                         // next ring slot
    const float* msrc = mplane + (size_t)(r0 - 5) * WW + cw + l16 * 4;
    const float* hsrc = hplane + (size_t)(r0 - 5) * WW + hcol;

    // ---- row fill (sequential): 16B cp.async; zeros for out-of-image rows ----
    auto fill_row = [&]() {
        float* bx = sbuf[fs][0];
        float* by = sbuf[fs][1];
        float* mdst = ((t < 16) ? bx : by) + 8 + l16 * 4;
        float* hdst = (hf ? by : bx) + hdoff;
        if ((unsigned)fr < (unsigned)HH) {
            unsigned d = (unsigned)__cvta_generic_to_shared(mdst);
            asm volatile("cp.async.cg.shared.global [%0], [%1], 16;" :: "r"(d), "l"(msrc) : "memory");
            if (hv) {
                unsigned dh = (unsigned)__cvta_generic_to_shared(hdst);
                asm volatile("cp.async.cg.shared.global [%0], [%1], 16;" :: "r"(dh), "l"(hsrc) : "memory");
            }
        } else {
            float4 z = make_float4(0.f, 0.f, 0.f, 0.f);
            *(float4*)mdst = z;
            if (hv) *(float4*)hdst = z;
        }
        ++fr;
        if (++fs == DEPTH) fs = 0;
        msrc += WW;
        hsrc += WW;
    };

    // prologue: prefetch rows 0..DIST-1, one commit group each
    #pragma unroll
    for (int p = 0; p < DIST; ++p) {
        fill_row();
        asm volatile("cp.async.commit_group;" ::: "memory");
    }

    // register ring: 11 rows x 4 packed fields (mu_x, mu_y, x^2+y^2, x*y)
    u64 RX[11], RY[11], RS[11], RP[11];
    float acc = 0.f;

    for (int blk = 0; blk < 7; ++blk) {
        #pragma unroll
        for (int ph = 0; ph < 11; ++ph) {
            const int pr = blk * 11 + ph;
            if (pr < NSTEP) {
                // warp-private pipeline: slot (pr+6)&7 = (pr-2)&7 was consumed
                // by this warp two iterations ago -> no block barrier needed.
                if (pr + DIST < NSTEP) fill_row();
                asm volatile("cp.async.commit_group;" ::: "memory");
                asm volatile("cp.async.wait_group %0;" :: "n"(DIST) : "memory");
                __syncwarp();   // make warp-mates' staged row visible

                // stage 14 floats per field into registers (aligned float2 loads)
                const float2* xv = (const float2*)sbuf[pr & 7][0] + (t + 1);
                const float2* yv = (const float2*)sbuf[pr & 7][1] + (t + 1);
                float xr[14], yr[14];
                #pragma unroll
                for (int i = 0; i < 7; ++i) {
                    float2 a = xv[i]; xr[2 * i] = a.x; xr[2 * i + 1] = a.y;
                    float2 c = yv[i]; yr[2 * i] = c.x; yr[2 * i + 1] = c.y;
                }

                // horizontal 11-tap conv, packed over column pair (cw+2t, cw+2t+1)
                u64 hx = 0, hy = 0, hsum = 0, hp = 0;
                #pragma unroll
                for (int j = 0; j < 11; ++j) {
                    u64 ax = pk2(xr[1 + j], xr[2 + j]);
                    u64 ay = pk2(yr[1 + j], yr[2 + j]);
                    hx = f2fma(g2[j], ax, hx);
                    hy = f2fma(g2[j], ay, hy);
                    u64 ss = f2mul(ax, ax);
                    ss = f2fma(ay, ay, ss);
                    hsum = f2fma(g2[j], ss, hsum);
                    u64 pp = f2mul(ax, ay);
                    hp = f2fma(g2[j], pp, hp);
                }
                RX[ph] = hx; RY[ph] = hy; RS[ph] = hsum; RP[ph] = hp;

                // vertical 11-tap conv + SSIM once ring is warm
                if (pr >= 10) {
                    u64 mx = f2mul(g2[0], RX[(ph + 1) % 11]);
                    u64 my = f2mul(g2[0], RY[(ph + 1) % 11]);
                    u64 sp = f2mul(g2[0], RS[(ph + 1) % 11]);
                    u64 sx = f2mul(g2[0], RP[(ph + 1) % 11]);
                    #pragma unroll
                    for (int k = 1; k < 11; ++k) {
                        const int sl = (ph + 1 + k) % 11;
                        mx = f2fma(g2[k], RX[sl], mx);
                        my = f2fma(g2[k], RY[sl], my);
                        sp = f2fma(g2[k], RS[sl], sp);
                        sx = f2fma(g2[k], RP[sl], sx);
                    }
                    u64 mx2 = f2mul(mx, mx);
                    u64 my2 = f2mul(my, my);
                    u64 mxy = f2mul(mx, my);
                    u64 msq = f2add(mx2, my2);
                    u64 vp  = f2fma(msq, NEG1, sp);    // sigma_x^2 + sigma_y^2
                    u64 vxy = f2fma(mxy, NEG1, sx);    // sigma_xy
                    u64 t1  = f2add(mxy, HC1);
                    u64 t2  = f2add(vxy, HC2);
                    u64 num = f2mul(t1, t2);           // ssim = 4*num/den
                    u64 t3  = f2add(msq, FC1);
                    u64 t4  = f2add(vp,  FC2);
                    u64 den = f2mul(t3, t4);
                    float n0, n1, d0, d1;
                    upk2(num, n0, n1);
                    upk2(den, d0, d1);
                    acc += __fdividef(n0, d0) + __fdividef(n1, d1);
                }
            }
        }
    }

    // ---- deterministic warp reduction -> partial ----
    #pragma unroll
    for (int o = 16; o; o >>= 1) acc += __shfl_down_sync(0xFFFFFFFFu, acc, o);

    int last = 0;
    if (t == 0) {
        g_partials[blockIdx.y * (NROWT * NSTRIP) + blockIdx.x] = acc;
        __threadfence();
        unsigned old = atomicAdd(&g_ticket, 1u);
        last = (old == NPART - 1);
    }
    last = __shfl_sync(0xFFFFFFFFu, last, 0);

    // ---- last warp: fixed-order final reduction (deterministic) ----
    if (last) {
        __threadfence();
        float v = 0.f;
        #pragma unroll
        for (int k = 0; k < NPART / 32; ++k)
            v += g_partials[t + 32 * k];
        #pragma unroll
        for (int o = 16; o; o >>= 1) v += __shfl_down_sync(0xFFFFFFFFu, v, o);
        if (t == 0) {
            // accumulated terms were num/4 / den -> scale by 4 / (B*H*W)
            out[0] = v * (4.0f / 16777216.0f);
            g_ticket = 0;   // reset for next graph replay
        }
    }
}

extern "C" void kernel_launch(void* const* d_in, const int* in_sizes, int n_in,
                              void* d_out, int out_size)
{
    const float* x   = (const float*)d_in[0];
    const float* y   = (const float*)d_in[1];
    const float* win = (const float*)d_in[2];
    float* out = (float*)d_out;

    dim3 grid(NROWT * NSTRIP, BATCH);   // (64, 64) = 4096 one-warp CTAs
    ssim_map_kernel<<<grid, 32>>>(x, y, win, out);
}

// round 14
// speedup vs baseline: 1.8128x; 1.0598x over previous
#include <cuda_runtime.h>
#include <cstdint>

#define BATCH 64
#define HH 512
#define WW 512
#define TILE_H 64
#define NROWT (HH / TILE_H)            // 8
#define NSTRIP 8                       // 64-col warp strips
#define NPART (BATCH * NROWT * NSTRIP) // 4096
#define DEPTH 8
#define DIST 6
#define NSTEP (TILE_H + 10)            // 74 staged rows per tile

typedef unsigned long long u64;

__device__ float g_partials[NPART];
__device__ unsigned int g_ticket = 0;

// ---- packed f32x2 helpers (Blackwell FFMA2 path, PTX-only) ----
__device__ __forceinline__ u64 pk2(float lo, float hi) {
    u64 r; asm("mov.b64 %0, {%1, %2};" : "=l"(r) : "f"(lo), "f"(hi)); return r;
}
__device__ __forceinline__ void upk2(u64 v, float& lo, float& hi) {
    asm("mov.b64 {%0, %1}, %2;" : "=f"(lo), "=f"(hi) : "l"(v));
}
__device__ __forceinline__ u64 f2mul(u64 a, u64 b) {
    u64 d; asm("mul.rn.f32x2 %0, %1, %2;" : "=l"(d) : "l"(a), "l"(b)); return d;
}
__device__ __forceinline__ u64 f2add(u64 a, u64 b) {
    u64 d; asm("add.rn.f32x2 %0, %1, %2;" : "=l"(d) : "l"(a), "l"(b)); return d;
}
__device__ __forceinline__ u64 f2fma(u64 a, u64 b, u64 c) {
    u64 d; asm("fma.rn.f32x2 %0, %1, %2, %3;" : "=l"(d) : "l"(a), "l"(b), "l"(c)); return d;
}

__global__ __launch_bounds__(32, 16)
void ssim_map_kernel(const float* __restrict__ x, const float* __restrict__ y,
                     const float* __restrict__ win, float* __restrict__ out)
{
    // warp-private staging ring: [slot][field][8 halo + 64 + 8 halo]  (5120 B)
    // 16B alignment REQUIRED for cp.async 16B destinations.
    __shared__ __align__(16) float sbuf[DEPTH][2][80];

    const int t     = threadIdx.x;          // 0..31
    const int strip = blockIdx.x & 7;
    const int rt    = blockIdx.x >> 3;
    const int b     = blockIdx.y;
    const int cw    = strip * 64;           // first output column of this warp
    const int r0    = rt * TILE_H;
    const float* xb = x + (size_t)b * HH * WW;
    const float* yb = y + (size_t)b * HH * WW;

    const bool lvalid = (cw > 0);
    const bool rvalid = (cw + 64 < WW);

    // zero ONLY invalid-side halos once (never written again)
    if (t < DEPTH) {
        float4 z = make_float4(0.f, 0.f, 0.f, 0.f);
        #pragma unroll
        for (int f = 0; f < 2; ++f) {
            if (!lvalid) { *(float4*)&sbuf[t][f][0]  = z; *(float4*)&sbuf[t][f][4]  = z; }
            if (!rvalid) { *(float4*)&sbuf[t][f][72] = z; *(float4*)&sbuf[t][f][76] = z; }
        }
    }

    // 1D taps g[i] = sum_j w2d[i][j] (sum g == 1), packed (g,g)
    u64 g2[11];
    #pragma unroll
    for (int i = 0; i < 11; ++i) {
        float s = 0.f;
        #pragma unroll
        for (int j = 0; j < 11; ++j) s += win[i * 11 + j];
        g2[i] = pk2(s, s);
    }

    const u64 HC1  = pk2(5e-5f, 5e-5f);     // C1/2
    const u64 HC2  = pk2(4.5e-4f, 4.5e-4f); // C2/2
    const u64 FC1  = pk2(1e-4f, 1e-4f);     // C1
    const u64 FC2  = pk2(9e-4f, 9e-4f);     // C2
    const u64 NEG1 = pk2(-1.f, -1.f);

    // lane roles for fills (computed once)
    const int  l16    = t & 15;
    const int  hf     = (t >> 2) & 1;        // halo field: 0=x, 1=y
    const int  hs     = (t >> 1) & 1;        // halo side: 0=left, 1=right
    const int  hk     = t & 1;               // halo chunk within side
    const bool hv     = (t < 8) && (hs ? rvalid : lvalid);
    const int  hdoff  = (hs ? 72 : 0) + hk * 4;
    const int  hcol   = hs ? (cw + 64 + hk * 4) : (cw - 8 + hk * 4);
    const float* mplane = (t < 16) ? xb : yb;
    const float* hplane = hf ? yb : xb;

    // running fill state (sequential rows): advance pointers by WW per fill
    int          fr   = r0 - 5;                                    // next row to fill
    int          fs   = 0;                                         // next ring slot
    const float* msrc = mplane + (size_t)(r0 - 5) * WW + cw + l16 * 4;
    const float* hsrc = hplane + (size_t)(r0 - 5) * WW + hcol;

    // ---- row fill (sequential): 16B cp.async; zeros for out-of-image rows ----
    auto fill_row = [&]() {
        float* bx = sbuf[fs][0];
        float* by = sbuf[fs][1];
        float* mdst = ((t < 16) ? bx : by) + 8 + l16 * 4;
        float* hdst = (hf ? by : bx) + hdoff;
        if ((unsigned)fr < (unsigned)HH) {
            unsigned d = (unsigned)__cvta_generic_to_shared(mdst);
            asm volatile("cp.async.cg.shared.global [%0], [%1], 16;" :: "r"(d), "l"(msrc) : "memory");
            if (hv) {
                unsigned dh = (unsigned)__cvta_generic_to_shared(hdst);
                asm volatile("cp.async.cg.shared.global [%0], [%1], 16;" :: "r"(dh), "l"(hsrc) : "memory");
            }
        } else {
            float4 z = make_float4(0.f, 0.f, 0.f, 0.f);
            *(float4*)mdst = z;
            if (hv) *(float4*)hdst = z;
        }
        ++fr;
        if (++fs == DEPTH) fs = 0;
        msrc += WW;
        hsrc += WW;
    };

    // prologue: prefetch rows 0..DIST-1, one commit group each
    #pragma unroll
    for (int p = 0; p < DIST; ++p) {
        fill_row();
        asm volatile("cp.async.commit_group;" ::: "memory");
    }

    // register ring: 11 rows x 4 packed fields (mu_x, mu_y, x^2+y^2, x*y)
    u64 RX[11], RY[11], RS[11], RP[11];
    float acc = 0.f;

    for (int blk = 0; blk < 7; ++blk) {
        #pragma unroll
        for (int ph = 0; ph < 11; ++ph) {
            const int pr = blk * 11 + ph;
            if (pr < NSTEP) {
                // warp-private pipeline: slot (pr+6)&7 = (pr-2)&7 was consumed
                // by this warp two iterations ago -> no block barrier needed.
                if (pr + DIST < NSTEP) fill_row();
                asm volatile("cp.async.commit_group;" ::: "memory");
                asm volatile("cp.async.wait_group %0;" :: "n"(DIST) : "memory");
                __syncwarp();   // make warp-mates' staged row visible

                // stage 14 floats per field into registers (aligned float2 loads)
                const float2* xv = (const float2*)sbuf[pr & 7][0] + (t + 1);
                const float2* yv = (const float2*)sbuf[pr & 7][1] + (t + 1);
                float xr[14], yr[14];
                #pragma unroll
                for (int i = 0; i < 7; ++i) {
                    float2 a = xv[i]; xr[2 * i] = a.x; xr[2 * i + 1] = a.y;
                    float2 c = yv[i]; yr[2 * i] = c.x; yr[2 * i + 1] = c.y;
                }

                // horizontal 11-tap conv, packed over column pair (cw+2t, cw+2t+1)
                u64 hx = 0, hy = 0, hsum = 0, hp = 0;
                #pragma unroll
                for (int j = 0; j < 11; ++j) {
                    u64 ax = pk2(xr[1 + j], xr[2 + j]);
                    u64 ay = pk2(yr[1 + j], yr[2 + j]);
                    hx = f2fma(g2[j], ax, hx);
                    hy = f2fma(g2[j], ay, hy);
                    u64 ss = f2mul(ax, ax);
                    ss = f2fma(ay, ay, ss);
                    hsum = f2fma(g2[j], ss, hsum);
                    u64 pp = f2mul(ax, ay);
                    hp = f2fma(g2[j], pp, hp);
                }
                RX[ph] = hx; RY[ph] = hy; RS[ph] = hsum; RP[ph] = hp;

                // vertical 11-tap conv + SSIM once ring is warm
                if (pr >= 10) {
                    u64 mx = f2mul(g2[0], RX[(ph + 1) % 11]);
                    u64 my = f2mul(g2[0], RY[(ph + 1) % 11]);
                    u64 sp = f2mul(g2[0], RS[(ph + 1) % 11]);
                    u64 sx = f2mul(g2[0], RP[(ph + 1) % 11]);
                    #pragma unroll
                    for (int k = 1; k < 11; ++k) {
                        const int sl = (ph + 1 + k) % 11;
                        mx = f2fma(g2[k], RX[sl], mx);
                        my = f2fma(g2[k], RY[sl], my);
                        sp = f2fma(g2[k], RS[sl], sp);
                        sx = f2fma(g2[k], RP[sl], sx);
                    }
                    u64 mx2 = f2mul(mx, mx);
                    u64 my2 = f2mul(my, my);
                    u64 mxy = f2mul(mx, my);
                    u64 msq = f2add(mx2, my2);
                    u64 vp  = f2fma(msq, NEG1, sp);    // sigma_x^2 + sigma_y^2
                    u64 vxy = f2fma(mxy, NEG1, sx);    // sigma_xy
                    u64 t1  = f2add(mxy, HC1);
                    u64 t2  = f2add(vxy, HC2);
                    u64 num = f2mul(t1, t2);           // ssim = 4*num/den
                    u64 t3  = f2add(msq, FC1);
                    u64 t4  = f2add(vp,  FC2);
                    u64 den = f2mul(t3, t4);
                    float n0, n1, d0, d1;
                    upk2(num, n0, n1);
                    upk2(den, d0, d1);
                    acc += __fdividef(n0, d0) + __fdividef(n1, d1);
                }
            }
        }
    }

    // ---- deterministic warp reduction -> partial ----
    #pragma unroll
    for (int o = 16; o; o >>= 1) acc += __shfl_down_sync(0xFFFFFFFFu, acc, o);

    int last = 0;
    if (t == 0) {
        g_partials[blockIdx.y * (NROWT * NSTRIP) + blockIdx.x] = acc;
        __threadfence();
        unsigned old = atomicAdd(&g_ticket, 1u);
        last = (old == NPART - 1);
    }
    last = __shfl_sync(0xFFFFFFFFu, last, 0);

    // ---- last warp: fixed-order final reduction (deterministic) ----
    if (last) {
        __threadfence();
        float v = 0.f;
        #pragma unroll
        for (int k = 0; k < NPART / 32; ++k)
            v += g_partials[t + 32 * k];
        #pragma unroll
        for (int o = 16; o; o >>= 1) v += __shfl_down_sync(0xFFFFFFFFu, v, o);
        if (t == 0) {
            // accumulated terms were num/4 / den -> scale by 4 / (B*H*W)
            out[0] = v * (4.0f / 16777216.0f);
            g_ticket = 0;   // reset for next graph replay
        }
    }
}

extern "C" void kernel_launch(void* const* d_in, const int* in_sizes, int n_in,
                              void* d_out, int out_size)
{
    const float* x   = (const float*)d_in[0];
    const float* y   = (const float*)d_in[1];
    const float* win = (const float*)d_in[2];
    float* out = (float*)d_out;

    dim3 grid(NROWT * NSTRIP, BATCH);   // (64, 64) = 4096 one-warp CTAs
    ssim_map_kernel<<<grid, 32>>>(x, y, win, out);
}